// round 10
// baseline (speedup 1.0000x reference)
#include <cuda_runtime.h>

#define N_ENT_MAX 100000
#define SPARSE_THRESHOLD 5

// Scratch (graph-capturable, no allocs). Zero-initialized at module load;
// the kernel self-resets all counters so every launch/replay starts clean.
__device__ int g_row_ptr[N_ENT_MAX + 1];
__device__ int g_worklist[N_ENT_MAX];
__device__ int g_count;
__device__ unsigned g_bar;
__device__ int g_done;

__device__ __forceinline__ void store_cs(float4* p, float4 v) {
    asm volatile("st.global.cs.v4.f32 [%0], {%1,%2,%3,%4};"
                 :: "l"(p), "f"(v.x), "f"(v.y), "f"(v.z), "f"(v.w) : "memory");
}

// ---------------------------------------------------------------------------
// Single persistent kernel, exactly one wave (148 SMs x 6 blocks resident,
// guaranteed by __launch_bounds__(256, 6) and grid=888).
//
//  Pre-barrier : (a) rowptr boundary-detect over sorted rows (int4 chunks)
//                (b) node classification -> worklist (warp-aggregated atomic)
//                    + zero-fill of masked output rows (overlaps (a))
//  Barrier     : atomic arrive + poll; release/acquire via threadfence.
//  Post-barrier: one warp per active node; unroll-8 512B row gathers
//                (R6/R9-proven core, ptxas front-batches the 8 LDG.128s).
//  Tail        : last-done block resets g_bar/g_count/g_done for replay.
// ---------------------------------------------------------------------------
__global__ void __launch_bounds__(256, 6)
fused_kernel(const float4* __restrict__ embeds,
             const int* __restrict__ degrees,
             const int* __restrict__ rows,
             const int* __restrict__ cols,
             float4* __restrict__ out,
             int n_ent, int n_edges)
{
    const int tid  = threadIdx.x;
    const int lane = tid & 31;
    const int gtid = blockIdx.x * blockDim.x + tid;
    const int nthreads = gridDim.x * blockDim.x;
    const int warp_global = gtid >> 5;
    const int total_warps = nthreads >> 5;
    const float4 z = make_float4(0.f, 0.f, 0.f, 0.f);

    // ---- Pre-barrier (a): rowptr build, 4 edges per thread step ----
    for (int t = gtid; t * 4 <= n_edges; t += nthreads) {
        int e0 = t * 4;
        int r[5];
        r[0] = (e0 > 0) ? rows[e0 - 1] : -1;
        if (e0 + 4 <= n_edges) {
            int4 v = *(const int4*)(rows + e0);
            r[1] = v.x; r[2] = v.y; r[3] = v.z; r[4] = v.w;
        } else {
            #pragma unroll
            for (int k = 0; k < 4; k++)
                r[k + 1] = (e0 + k < n_edges) ? rows[e0 + k] : n_ent;
        }
        #pragma unroll
        for (int k = 0; k < 4; k++) {
            int e = e0 + k;
            if (e > n_edges) break;
            for (int node = r[k] + 1; node <= r[k + 1]; node++)
                g_row_ptr[node] = e;
        }
    }

    // ---- Pre-barrier (b): classify nodes, build worklist, zero masked ----
    for (int base = warp_global * 32; base < n_ent; base += total_warps * 32) {
        int node = base + lane;
        bool valid  = (node < n_ent);
        bool active = valid && (degrees[node] <= SPARSE_THRESHOLD);

        unsigned act_mask = __ballot_sync(0xffffffffu, active);
        int n_act = __popc(act_mask);
        int ofs = 0;
        if (lane == 0 && n_act)
            ofs = atomicAdd(&g_count, n_act);
        ofs = __shfl_sync(0xffffffffu, ofs, 0);
        if (active) {
            int rank = __popc(act_mask & ((1u << lane) - 1u));
            g_worklist[ofs + rank] = node;
        }

        // Zero-fill masked rows (valid && !active), coalesced 512B stores.
        unsigned msk = __ballot_sync(0xffffffffu, valid && !active);
        while (msk) {
            int j = __ffs(msk) - 1;
            msk &= msk - 1u;
            store_cs(out + (size_t)(base + j) * 32 + lane, z);
        }
    }

    // ---- Grid barrier (all 888 blocks co-resident: one wave) ----
    __syncthreads();
    if (tid == 0) {
        __threadfence();                       // release our writes
        atomicAdd(&g_bar, 1u);
        while (atomicAdd(&g_bar, 0u) < (unsigned)gridDim.x)
            __nanosleep(128);
        __threadfence();                       // acquire others' writes
    }
    __syncthreads();

    // ---- Post-barrier: gather for active nodes ----
    const int n_active = g_count;
    for (int i = warp_global; i < n_active; i += total_warps) {
        const int node  = g_worklist[i];
        const int start = g_row_ptr[node];
        const int end   = g_row_ptr[node + 1];
        const int cnt   = end - start;

        float4 a0 = z, a1 = z;

        int e = start;
        for (; e + 8 <= end; e += 8) {
            int c0 = __ldg(cols + e);
            int c1 = __ldg(cols + e + 1);
            int c2 = __ldg(cols + e + 2);
            int c3 = __ldg(cols + e + 3);
            int c4 = __ldg(cols + e + 4);
            int c5 = __ldg(cols + e + 5);
            int c6 = __ldg(cols + e + 6);
            int c7 = __ldg(cols + e + 7);
            float4 v0 = __ldg(embeds + (size_t)c0 * 32 + lane);
            float4 v1 = __ldg(embeds + (size_t)c1 * 32 + lane);
            float4 v2 = __ldg(embeds + (size_t)c2 * 32 + lane);
            float4 v3 = __ldg(embeds + (size_t)c3 * 32 + lane);
            float4 v4 = __ldg(embeds + (size_t)c4 * 32 + lane);
            float4 v5 = __ldg(embeds + (size_t)c5 * 32 + lane);
            float4 v6 = __ldg(embeds + (size_t)c6 * 32 + lane);
            float4 v7 = __ldg(embeds + (size_t)c7 * 32 + lane);
            a0.x += (v0.x + v2.x) + (v4.x + v6.x);
            a0.y += (v0.y + v2.y) + (v4.y + v6.y);
            a0.z += (v0.z + v2.z) + (v4.z + v6.z);
            a0.w += (v0.w + v2.w) + (v4.w + v6.w);
            a1.x += (v1.x + v3.x) + (v5.x + v7.x);
            a1.y += (v1.y + v3.y) + (v5.y + v7.y);
            a1.z += (v1.z + v3.z) + (v5.z + v7.z);
            a1.w += (v1.w + v3.w) + (v5.w + v7.w);
        }
        for (; e < end; e++) {
            int c = __ldg(cols + e);
            float4 v = __ldg(embeds + (size_t)c * 32 + lane);
            a0.x += v.x; a0.y += v.y; a0.z += v.z; a0.w += v.w;
        }

        const float inv = 1.0f / (float)(cnt > 0 ? cnt : 1);
        float4 r;
        r.x = (a0.x + a1.x) * inv;
        r.y = (a0.y + a1.y) * inv;
        r.z = (a0.z + a1.z) * inv;
        r.w = (a0.w + a1.w) * inv;
        store_cs(out + (size_t)node * 32 + lane, r);
    }

    // ---- Tail: last-done block resets counters for the next launch ----
    __syncthreads();
    if (tid == 0) {
        int d = atomicAdd(&g_done, 1);
        if (d == (int)gridDim.x - 1) {
            __threadfence();
            g_count = 0;
            g_bar   = 0u;
            g_done  = 0;
        }
    }
}

extern "C" void kernel_launch(void* const* d_in, const int* in_sizes, int n_in,
                              void* d_out, int out_size)
{
    const float4* embeds  = (const float4*)d_in[0];  // [N_ENT, 128] f32
    const int*    degrees = (const int*)d_in[1];     // [N_ENT] i32
    const int*    rows    = (const int*)d_in[2];     // [E] i32 (sorted)
    const int*    cols    = (const int*)d_in[3];     // [E] i32

    const int n_ent   = in_sizes[1];
    const int n_edges = in_sizes[2];
    float4* out = (float4*)d_out;

    // Exactly one resident wave: 148 SMs x 6 blocks (launch_bounds 256,6).
    fused_kernel<<<148 * 6, 256>>>(embeds, degrees, rows, cols, out,
                                   n_ent, n_edges);
}